// round 5
// baseline (speedup 1.0000x reference)
#include <cuda_runtime.h>
#include <cstdint>

#define B_   8
#define LQ_  2048
#define LK_  2048
#define D_   1024
#define DV_  1024

// ---------------- scratch (device globals; no runtime allocation) ----------------
__device__ float g_qW[(long)B_ * LQ_ * D_];   // query @ W        [B*LQ, D]
__device__ float g_kT[(long)B_ * D_ * LK_];   // key transposed   [B][D][LK]

// ---------------- helpers ----------------
__device__ __forceinline__ uint32_t smem_u32(const void* p) {
    uint32_t a;
    asm("{ .reg .u64 t; cvta.to.shared.u64 t, %1; cvt.u32.u64 %0, t; }" : "=r"(a) : "l"(p));
    return a;
}

__device__ __forceinline__ uint32_t f2tf32(float x) {
    uint32_t u;
    asm("cvt.rna.tf32.f32 %0, %1;" : "=r"(u) : "f"(x));
    return u;
}

// split fp32 -> (tf32 hi, fp32-bits lo). lo is passed raw to the MMA: the
// tensor core truncates operand mantissas to tf32, and lo has <=12 significant
// bits, so the truncation residual is ~2^-24 relative. 2 ops instead of 3.
__device__ __forceinline__ void split_tf32(float x, uint32_t& h, uint32_t& l) {
    h = f2tf32(x);
    l = __float_as_uint(x - __uint_as_float(h));
}

__device__ __forceinline__ void mma_tf32(float* d, const uint32_t* a, const uint32_t* b) {
    asm volatile(
        "mma.sync.aligned.m16n8k8.row.col.f32.tf32.tf32.f32 "
        "{%0,%1,%2,%3}, {%4,%5,%6,%7}, {%8,%9}, {%0,%1,%2,%3};"
        : "+f"(d[0]), "+f"(d[1]), "+f"(d[2]), "+f"(d[3])
        : "r"(a[0]), "r"(a[1]), "r"(a[2]), "r"(a[3]),
          "r"(b[0]), "r"(b[1]));
}

// bulk async copy: one row per instruction, completion via mbarrier tx-bytes
__device__ __forceinline__ void bulk_ldgsts(uint32_t dst, const void* src,
                                            uint32_t bytes, uint32_t mbar) {
    asm volatile("mbarrier.arrive.expect_tx.shared.b64 _, [%0], %1;"
                 :: "r"(mbar), "r"(bytes) : "memory");
    asm volatile("cp.async.bulk.shared::cluster.global.mbarrier::complete_tx::bytes "
                 "[%0], [%1], %2, [%3];"
                 :: "r"(dst), "l"(src), "r"(bytes), "r"(mbar) : "memory");
}

#define MBARRIER_INIT(m, c) \
    asm volatile("mbarrier.init.shared.b64 [%0], %1;" :: "r"(m), "r"(c) : "memory")

#define MBARRIER_WAIT_PARITY(mbar_smem_addr, phase_parity) do { \
    uint32_t _mbar = (uint32_t)(mbar_smem_addr); \
    uint32_t _parity = (uint32_t)(phase_parity); \
    uint32_t _done; \
    asm volatile( \
        "{\n\t.reg .pred p;\n\t" \
        "mbarrier.try_wait.parity.acquire.cta.shared::cta.b64 p, [%1], %2;\n\t" \
        "selp.b32 %0, 1, 0, p;\n\t}" \
        : "=r"(_done) : "r"(_mbar), "r"(_parity) : "memory"); \
    if (!_done) { \
        asm volatile( \
            "{\n\t.reg .pred P1;\n\t" \
            "WAIT_LOOP_%=:\n\t" \
            "mbarrier.try_wait.parity.acquire.cta.shared::cta.b64 P1, [%0], %1, 0x989680;\n\t" \
            "@P1 bra.uni WAIT_DONE_%=;\n\t" \
            "bra.uni WAIT_LOOP_%=;\n\t" \
            "WAIT_DONE_%=:\n\t}" \
            :: "r"(_mbar), "r"(_parity) : "memory"); \
    } \
} while (0)

// ---------------- GEMM config ----------------
#define BM 128
#define BN 128
#define BK 32
#define STAGES 3
#define LDA_S 36                        // floats: 32 + 4 pad (row pitch 144B, 16B-mult)
#define LDB_S 132                       // floats: 128 + 4 pad (row pitch 528B, 16B-mult)
#define A_FLOATS (BM * LDA_S)           // 4608
#define B_FLOATS (BK * LDB_S)           // 4224
#define STAGE_BYTES ((A_FLOATS + B_FLOATS) * 4)   // 35328
#define SMEM_BASE 128                   // mbarriers live in [0,128)
#define GEMM_SMEM (SMEM_BASE + STAGES * STAGE_BYTES)
#define TX_BYTES_A 128u                 // per A row
#define TX_BYTES_B 512u                 // per B row
#define FILL_THREADS 160                // 128 A rows + 32 B rows

// C[M,N] = A[M,K] @ B[K,N], fp32 in / fp32 out, 3xTF32 tensor-core emulation.
// A row-major [M,K], B row-major [K,N]. Batched via blockIdx.z strides.
__global__ __launch_bounds__(256, 1) void gemm3x_tf32(
    const float* __restrict__ A, const float* __restrict__ Bm, float* __restrict__ C,
    int M, int N, int K, long sA, long sB, long sC)
{
    extern __shared__ float sf[];
    const uint32_t sbase = smem_u32(sf);

    A  += (long)blockIdx.z * sA;
    Bm += (long)blockIdx.z * sB;
    C  += (long)blockIdx.z * sC;

    const int tid  = threadIdx.x;
    const int lane = tid & 31;
    const int warp = tid >> 5;
    const int g    = lane >> 2;          // groupID (0..7)
    const int t    = lane & 3;           // threadID_in_group (0..3)
    const int wm   = (warp >> 2) * 64;   // warp M offset (0/64)
    const int wn   = (warp & 3) * 32;    // warp N offset (0/32/64/96)
    const int m0   = blockIdx.y * BM;
    const int n0   = blockIdx.x * BN;

    // mbarrier init: one per stage, 160 arrivals (each filler thread arrives
    // via its expect_tx) + tx bytes per stage.
    if (tid == 0) {
        #pragma unroll
        for (int s = 0; s < STAGES; s++) MBARRIER_INIT(sbase + 8 * s, FILL_THREADS);
    }
    __syncthreads();

    // stage fill: 160 bulk copies, one per thread
    auto fill_stage = [&](int buf, int itk) {
        if (tid < FILL_THREADS) {
            const uint32_t mbar = sbase + 8 * buf;
            const uint32_t st   = sbase + SMEM_BASE + buf * STAGE_BYTES;
            const int k0 = itk * BK;
            if (tid < BM) {
                bulk_ldgsts(st + (uint32_t)tid * (LDA_S * 4),
                            A + (long)(m0 + tid) * K + k0, TX_BYTES_A, mbar);
            } else {
                const int r = tid - BM;
                bulk_ldgsts(st + (uint32_t)(A_FLOATS * 4) + (uint32_t)r * (LDB_S * 4),
                            Bm + (long)(k0 + r) * N + n0, TX_BYTES_B, mbar);
            }
        }
    };

    float acc[64];
    #pragma unroll
    for (int i = 0; i < 64; i++) acc[i] = 0.0f;

    const int iters = K / BK;

    fill_stage(0, 0);
    fill_stage(1, 1);

    for (int it = 0; it < iters; it++) {
        const int buf = it % STAGES;
        MBARRIER_WAIT_PARITY(sbase + 8 * buf, (it / STAGES) & 1);
        __syncthreads();   // all threads done reading buffer (it-1)%3 == (it+2)%3

        if (it + 2 < iters) fill_stage((it + 2) % STAGES, it + 2);

        const float* As = sf + (SMEM_BASE / 4) + buf * (STAGE_BYTES / 4);
        const float* Bs = As + A_FLOATS;

        #pragma unroll
        for (int kk = 0; kk < BK; kk += 8) {
            uint32_t ah[16], al[16], bh[8], bl[8];
            #pragma unroll
            for (int mi = 0; mi < 4; mi++) {
                const int r = wm + mi * 16 + g;
                split_tf32(As[r * LDA_S + kk + t],           ah[mi * 4 + 0], al[mi * 4 + 0]);
                split_tf32(As[(r + 8) * LDA_S + kk + t],     ah[mi * 4 + 1], al[mi * 4 + 1]);
                split_tf32(As[r * LDA_S + kk + t + 4],       ah[mi * 4 + 2], al[mi * 4 + 2]);
                split_tf32(As[(r + 8) * LDA_S + kk + t + 4], ah[mi * 4 + 3], al[mi * 4 + 3]);
            }
            #pragma unroll
            for (int nj = 0; nj < 4; nj++) {
                const int c = wn + nj * 8 + g;
                split_tf32(Bs[(kk + t) * LDB_S + c],     bh[nj * 2 + 0], bl[nj * 2 + 0]);
                split_tf32(Bs[(kk + t + 4) * LDB_S + c], bh[nj * 2 + 1], bl[nj * 2 + 1]);
            }
            #pragma unroll
            for (int mi = 0; mi < 4; mi++)
                #pragma unroll
                for (int nj = 0; nj < 4; nj++) {
                    float* d = acc + (mi * 4 + nj) * 4;
                    mma_tf32(d, &ah[mi * 4], &bh[nj * 2]);   // hi*hi
                    mma_tf32(d, &ah[mi * 4], &bl[nj * 2]);   // hi*lo
                    mma_tf32(d, &al[mi * 4], &bh[nj * 2]);   // lo*hi
                }
        }
        __syncthreads();
    }

    // ---- epilogue: direct fp32 stores ----
    #pragma unroll
    for (int mi = 0; mi < 4; mi++) {
        #pragma unroll
        for (int nj = 0; nj < 4; nj++) {
            const float* d = acc + (mi * 4 + nj) * 4;
            const long row = m0 + wm + mi * 16 + g;
            const long col = n0 + wn + nj * 8 + 2 * t;
            *reinterpret_cast<float2*>(C + row * N + col)       = make_float2(d[0], d[1]);
            *reinterpret_cast<float2*>(C + (row + 8) * N + col) = make_float2(d[2], d[3]);
        }
    }
}

// ---------------- transpose: in[R,C] -> out[C,R], batched ----------------
__global__ __launch_bounds__(256) void transpose_f32(
    const float* __restrict__ in, float* __restrict__ out,
    int R, int C, long sIn, long sOut)
{
    __shared__ float tb[32][33];
    const float* ip = in + (long)blockIdx.z * sIn;
    float* op = out + (long)blockIdx.z * sOut;
    const int c0 = blockIdx.x * 32;
    const int r0 = blockIdx.y * 32;
    const int tx = threadIdx.x;   // 0..31
    const int ty = threadIdx.y;   // 0..7

    #pragma unroll
    for (int i = 0; i < 4; i++)
        tb[ty + 8 * i][tx] = ip[(long)(r0 + ty + 8 * i) * C + c0 + tx];
    __syncthreads();

    #pragma unroll
    for (int i = 0; i < 4; i++) {
        const int orow = ty + 8 * i;
        op[(long)(c0 + orow) * R + r0 + tx] = tb[tx][orow];
    }
}

// ---------------- softmax over 2048 cols, in place ----------------
__inline__ __device__ float warpMax(float v) {
    #pragma unroll
    for (int o = 16; o > 0; o >>= 1) v = fmaxf(v, __shfl_xor_sync(0xffffffffu, v, o));
    return v;
}
__inline__ __device__ float warpSum(float v) {
    #pragma unroll
    for (int o = 16; o > 0; o >>= 1) v += __shfl_xor_sync(0xffffffffu, v, o);
    return v;
}

__global__ __launch_bounds__(256) void softmax2048(float* __restrict__ S)
{
    __shared__ float red[8];
    float4* b4 = reinterpret_cast<float4*>(S + (long)blockIdx.x * 2048);

    float4 v0 = b4[threadIdx.x];
    float4 v1 = b4[threadIdx.x + 256];

    float m = fmaxf(fmaxf(fmaxf(v0.x, v0.y), fmaxf(v0.z, v0.w)),
                    fmaxf(fmaxf(v1.x, v1.y), fmaxf(v1.z, v1.w)));
    m = warpMax(m);
    const int wid = threadIdx.x >> 5, lid = threadIdx.x & 31;
    if (lid == 0) red[wid] = m;
    __syncthreads();
    float bm = red[0];
    #pragma unroll
    for (int i = 1; i < 8; i++) bm = fmaxf(bm, red[i]);
    __syncthreads();

    v0.x = __expf(v0.x - bm); v0.y = __expf(v0.y - bm);
    v0.z = __expf(v0.z - bm); v0.w = __expf(v0.w - bm);
    v1.x = __expf(v1.x - bm); v1.y = __expf(v1.y - bm);
    v1.z = __expf(v1.z - bm); v1.w = __expf(v1.w - bm);

    float s = (v0.x + v0.y) + (v0.z + v0.w) + (v1.x + v1.y) + (v1.z + v1.w);
    s = warpSum(s);
    if (lid == 0) red[wid] = s;
    __syncthreads();
    float bs = 0.f;
    #pragma unroll
    for (int i = 0; i < 8; i++) bs += red[i];
    const float inv = 1.0f / bs;

    v0.x *= inv; v0.y *= inv; v0.z *= inv; v0.w *= inv;
    v1.x *= inv; v1.y *= inv; v1.z *= inv; v1.w *= inv;
    b4[threadIdx.x]       = v0;
    b4[threadIdx.x + 256] = v1;
}

// ---------------- launch ----------------
extern "C" void kernel_launch(void* const* d_in, const int* in_sizes, int n_in,
                              void* d_out, int out_size)
{
    const float* key   = (const float*)d_in[0];
    const float* query = (const float*)d_in[1];
    const float* value = (const float*)d_in[2];
    const float* W     = (const float*)d_in[3];
    // bias (d_in[4]): scalar added to every score -> softmax-invariant -> no effect
    // on either output; intentionally unused.

    float* weights = (float*)d_out;                   // [B, LQ, LK]
    float* ctx     = weights + (long)B_ * LQ_ * LK_;  // [B, LQ, DV]

    float *qW, *kT;
    cudaGetSymbolAddress((void**)&qW, g_qW);
    cudaGetSymbolAddress((void**)&kT, g_kT);

    cudaFuncSetAttribute(gemm3x_tf32, cudaFuncAttributeMaxDynamicSharedMemorySize, GEMM_SMEM);

    // 0) kT[b][e][lk] = key[b][lk][e]
    transpose_f32<<<dim3(D_ / 32, LK_ / 32, B_), dim3(32, 8)>>>(
        key, kT, LK_, D_, (long)LK_ * D_, (long)D_ * LK_);

    // 1) qW = query @ W : [16384,1024] x [1024,1024]
    gemm3x_tf32<<<dim3(D_ / BN, (B_ * LQ_) / BM, 1), 256, GEMM_SMEM>>>(
        query, W, qW, B_ * LQ_, D_, D_, 0, 0, 0);

    // 2) scores = qW @ kT (per batch): [2048,1024] x [1024,2048] -> weights region
    gemm3x_tf32<<<dim3(LK_ / BN, LQ_ / BM, B_), 256, GEMM_SMEM>>>(
        qW, kT, weights, LQ_, LK_, D_,
        (long)LQ_ * D_, (long)D_ * LK_, (long)LQ_ * LK_);

    // 3) softmax rows in place
    softmax2048<<<B_ * LQ_, 256>>>(weights);

    // 4) ctx = weights @ value (per batch): [2048,2048] x [2048,1024]
    gemm3x_tf32<<<dim3(DV_ / BN, LQ_ / BM, B_), 256, GEMM_SMEM>>>(
        weights, value, ctx, LQ_, DV_, LK_,
        (long)LQ_ * LK_, (long)LK_ * DV_, (long)LQ_ * DV_);
}

// round 6
// speedup vs baseline: 1.4253x; 1.4253x over previous
#include <cuda_runtime.h>
#include <cstdint>

#define B_   8
#define LQ_  2048
#define LK_  2048
#define D_   1024
#define DV_  1024

// ---------------- tiled scratch (device globals) ----------------
// All tiled arrays: sequence of 16KB tiles [128 rows x 32 floats], element (r,c)
// stored at float offset r*32 + (c ^ ((r&7)<<2)).
__device__ float g_qT [(long)B_ * LQ_ * D_];    // query tiled  [rows/128][K/32]
__device__ float g_kT [(long)B_ * LK_ * D_];    // key tiled (B-side of GEMM2)
__device__ float g_WtT[(long)D_ * D_];          // W^T tiled (B-side of GEMM1)
__device__ float g_vTT[(long)B_ * DV_ * LK_];   // value^T tiled (B-side of GEMM3)
__device__ float g_qWT[(long)B_ * LQ_ * D_];    // qW tiled (A-side of GEMM2)
__device__ float g_wT [(long)B_ * LQ_ * LK_];   // weights tiled (A-side of GEMM3)

// ---------------- helpers ----------------
__device__ __forceinline__ uint32_t smem_u32(const void* p) {
    uint32_t a;
    asm("{ .reg .u64 t; cvta.to.shared.u64 t, %1; cvt.u32.u64 %0, t; }" : "=r"(a) : "l"(p));
    return a;
}

__device__ __forceinline__ uint32_t f2tf32(float x) {
    uint32_t u;
    asm("cvt.rna.tf32.f32 %0, %1;" : "=r"(u) : "f"(x));
    return u;
}

// split fp32 -> (tf32 hi, fp32-bits lo); lo passed raw (HMMA truncates it).
__device__ __forceinline__ void split_tf32(float x, uint32_t& h, uint32_t& l) {
    h = f2tf32(x);
    l = __float_as_uint(x - __uint_as_float(h));
}

__device__ __forceinline__ void mma_tf32(float* d, const uint32_t* a, const uint32_t* b) {
    asm volatile(
        "mma.sync.aligned.m16n8k8.row.col.f32.tf32.tf32.f32 "
        "{%0,%1,%2,%3}, {%4,%5,%6,%7}, {%8,%9}, {%0,%1,%2,%3};"
        : "+f"(d[0]), "+f"(d[1]), "+f"(d[2]), "+f"(d[3])
        : "r"(a[0]), "r"(a[1]), "r"(a[2]), "r"(a[3]),
          "r"(b[0]), "r"(b[1]));
}

__device__ __forceinline__ void bulk_cp(uint32_t dst, const void* src,
                                        uint32_t bytes, uint32_t mbar) {
    asm volatile("cp.async.bulk.shared::cluster.global.mbarrier::complete_tx::bytes "
                 "[%0], [%1], %2, [%3];"
                 :: "r"(dst), "l"(src), "r"(bytes), "r"(mbar) : "memory");
}

#define MBARRIER_INIT(m, c) \
    asm volatile("mbarrier.init.shared.b64 [%0], %1;" :: "r"(m), "r"(c) : "memory")
#define MBARRIER_EXPECT_TX(m, b) \
    asm volatile("mbarrier.arrive.expect_tx.shared.b64 _, [%0], %1;" :: "r"(m), "r"(b) : "memory")

#define MBARRIER_WAIT_PARITY(mbar_smem_addr, phase_parity) do { \
    uint32_t _mbar = (uint32_t)(mbar_smem_addr); \
    uint32_t _parity = (uint32_t)(phase_parity); \
    uint32_t _done; \
    asm volatile( \
        "{\n\t.reg .pred p;\n\t" \
        "mbarrier.try_wait.parity.acquire.cta.shared::cta.b64 p, [%1], %2;\n\t" \
        "selp.b32 %0, 1, 0, p;\n\t}" \
        : "=r"(_done) : "r"(_mbar), "r"(_parity) : "memory"); \
    if (!_done) { \
        asm volatile( \
            "{\n\t.reg .pred P1;\n\t" \
            "WAIT_LOOP_%=:\n\t" \
            "mbarrier.try_wait.parity.acquire.cta.shared::cta.b64 P1, [%0], %1, 0x989680;\n\t" \
            "@P1 bra.uni WAIT_DONE_%=;\n\t" \
            "bra.uni WAIT_LOOP_%=;\n\t" \
            "WAIT_DONE_%=:\n\t}" \
            :: "r"(_mbar), "r"(_parity) : "memory"); \
    } \
} while (0)

// ---------------- GEMM config ----------------
#define STAGES 4
#define TILE_FLOATS 4096                 // 128 x 32
#define TILE_BYTES  16384
#define STAGE_BYTES (2 * TILE_BYTES)     // A tile + B tile
#define SMEM_BASE   1024                 // mbarriers region
#define GEMM_SMEM   (SMEM_BASE + STAGES * STAGE_BYTES)

// C[M,N] = A[M,K] @ Bt[N,K]^T. A, Bt are TILED (16KB tiles as above).
// TILED_C: write C in tiled-swizzled layout too (for feeding the next GEMM).
template<bool TILED_C>
__global__ __launch_bounds__(256, 1) void gemm3x_tf32(
    const float* __restrict__ A, const float* __restrict__ Bt, float* __restrict__ C,
    int M, int N, int K, long sA, long sB, long sC)
{
    extern __shared__ float sf[];
    const uint32_t sbase = smem_u32(sf);

    A  += (long)blockIdx.z * sA;
    Bt += (long)blockIdx.z * sB;
    C  += (long)blockIdx.z * sC;

    const int tid  = threadIdx.x;
    const int lane = tid & 31;
    const int warp = tid >> 5;
    const int g    = lane >> 2;          // 0..7
    const int t    = lane & 3;           // 0..3
    const int sw   = g << 2;             // per-thread column swizzle
    const int wm   = (warp >> 2) * 64;   // warp M offset (0/64)
    const int wn   = (warp & 3) * 32;    // warp N offset (0/32/64/96)
    const int Kb   = K >> 5;

    if (tid == 0) {
        #pragma unroll
        for (int s = 0; s < STAGES; s++) MBARRIER_INIT(sbase + 8 * s, 1);
    }
    __syncthreads();

    auto fill = [&](int it2) {
        if (tid == 0) {
            const int buf = it2 & (STAGES - 1);
            const uint32_t mbar = sbase + 8 * buf;
            const uint32_t st   = sbase + SMEM_BASE + buf * STAGE_BYTES;
            MBARRIER_EXPECT_TX(mbar, STAGE_BYTES);
            bulk_cp(st,              A  + ((long)blockIdx.y * Kb + it2) * TILE_FLOATS,
                    TILE_BYTES, mbar);
            bulk_cp(st + TILE_BYTES, Bt + ((long)blockIdx.x * Kb + it2) * TILE_FLOATS,
                    TILE_BYTES, mbar);
        }
    };

    float acc[64];
    #pragma unroll
    for (int i = 0; i < 64; i++) acc[i] = 0.0f;

    fill(0); fill(1); fill(2);

    for (int it = 0; it < Kb; it++) {
        const int buf = it & (STAGES - 1);
        if (it + 3 < Kb) fill(it + 3);   // reuses buffer (it-1): reads done (sync below)
        MBARRIER_WAIT_PARITY(sbase + 8 * buf, (it >> 2) & 1);

        const float* As = sf + (SMEM_BASE / 4) + buf * (STAGE_BYTES / 4);
        const float* Bs = As + TILE_FLOATS;

        #pragma unroll
        for (int kk = 0; kk < 32; kk += 8) {
            const int c0 = (kk + t) ^ sw;
            const int c1 = (kk + t + 4) ^ sw;
            uint32_t ah[16], al[16], bh[8], bl[8];
            #pragma unroll
            for (int mi = 0; mi < 4; mi++) {
                const int r = wm + mi * 16 + g;
                split_tf32(As[r * 32 + c0],       ah[mi * 4 + 0], al[mi * 4 + 0]);
                split_tf32(As[(r + 8) * 32 + c0], ah[mi * 4 + 1], al[mi * 4 + 1]);
                split_tf32(As[r * 32 + c1],       ah[mi * 4 + 2], al[mi * 4 + 2]);
                split_tf32(As[(r + 8) * 32 + c1], ah[mi * 4 + 3], al[mi * 4 + 3]);
            }
            #pragma unroll
            for (int nj = 0; nj < 4; nj++) {
                const int rr = wn + nj * 8 + g;
                split_tf32(Bs[rr * 32 + c0], bh[nj * 2 + 0], bl[nj * 2 + 0]);
                split_tf32(Bs[rr * 32 + c1], bh[nj * 2 + 1], bl[nj * 2 + 1]);
            }
            #pragma unroll
            for (int mi = 0; mi < 4; mi++)
                #pragma unroll
                for (int nj = 0; nj < 4; nj++) {
                    float* d = acc + (mi * 4 + nj) * 4;
                    mma_tf32(d, &ah[mi * 4], &bh[nj * 2]);   // hi*hi
                    mma_tf32(d, &ah[mi * 4], &bl[nj * 2]);   // hi*lo
                    mma_tf32(d, &al[mi * 4], &bh[nj * 2]);   // lo*hi
                }
        }
        __syncthreads();
    }

    // ---- epilogue ----
    const int m0 = blockIdx.y * 128;
    const int n0 = blockIdx.x * 128;
    #pragma unroll
    for (int mi = 0; mi < 4; mi++) {
        #pragma unroll
        for (int nj = 0; nj < 4; nj++) {
            const float* d = acc + (mi * 4 + nj) * 4;
            const int row = m0 + wm + mi * 16 + g;
            const int col = n0 + wn + nj * 8 + 2 * t;
            if (TILED_C) {
                // tiled-swizzled write: tile (row>>7, col>>5)
                const int c31 = (col & 31);
                #pragma unroll
                for (int h = 0; h < 2; h++) {
                    const int rr = row + 8 * h;
                    const long off = ((long)(rr >> 7) * (N >> 5) + (col >> 5)) * TILE_FLOATS
                                   + (rr & 127) * 32 + (c31 ^ ((rr & 7) << 2));
                    *reinterpret_cast<float2*>(C + off) = make_float2(d[2 * h], d[2 * h + 1]);
                }
            } else {
                *reinterpret_cast<float2*>(C + (long)row * N + col)       = make_float2(d[0], d[1]);
                *reinterpret_cast<float2*>(C + (long)(row + 8) * N + col) = make_float2(d[2], d[3]);
            }
        }
    }
}

// ---------------- retile: [rows,C] row-major -> tiles [rows/128][C/32] swizzled ----------------
__global__ __launch_bounds__(256) void retile(const float* __restrict__ in,
                                              float* __restrict__ out, int C)
{
    const int rb = blockIdx.y, kb = blockIdx.x;
    float* otile = out + ((long)rb * (C >> 5) + kb) * TILE_FLOATS;
    #pragma unroll
    for (int i = 0; i < 4; i++) {
        const int id = threadIdx.x + 256 * i;   // 0..1023 (float4 units)
        const int r = id >> 3;
        const int c4 = (id & 7) << 2;
        float4 v = *reinterpret_cast<const float4*>(
            in + (long)(rb * 128 + r) * C + kb * 32 + c4);
        *reinterpret_cast<float4*>(otile + r * 32 + (c4 ^ ((r & 7) << 2))) = v;
    }
}

// ---------------- transpose + tile: in[R,C] -> tiles of in^T ([C/128][R/32]) ----------------
__global__ __launch_bounds__(256) void transpose_tile(
    const float* __restrict__ in, float* __restrict__ out,
    int R, int C, long sIn, long sOut)
{
    __shared__ float tb[32][33];
    const float* ip = in + (long)blockIdx.z * sIn;
    float* op = out + (long)blockIdx.z * sOut;
    const int k0 = blockIdx.x * 32;   // row block of in (K dim)
    const int n0 = blockIdx.y * 32;   // col block of in (N dim)
    const int tx = threadIdx.x & 31;
    const int ty = threadIdx.x >> 5;  // 0..7

    #pragma unroll
    for (int i = 0; i < 4; i++)
        tb[ty + 8 * i][tx] = ip[(long)(k0 + ty + 8 * i) * C + n0 + tx];
    __syncthreads();

    const int nb = n0 >> 7, kb = k0 >> 5;
    float* otile = op + ((long)nb * (R >> 5) + kb) * TILE_FLOATS;
    #pragma unroll
    for (int i = 0; i < 4; i++) {
        const int n_loc = ty + 8 * i;
        const int rt = (n0 & 127) + n_loc;
        otile[rt * 32 + (tx ^ ((rt & 7) << 2))] = tb[tx][n_loc];
    }
}

// ---------------- softmax over 2048 cols, in place + tiled-swizzled copy ----------------
__inline__ __device__ float warpMax(float v) {
    #pragma unroll
    for (int o = 16; o > 0; o >>= 1) v = fmaxf(v, __shfl_xor_sync(0xffffffffu, v, o));
    return v;
}
__inline__ __device__ float warpSum(float v) {
    #pragma unroll
    for (int o = 16; o > 0; o >>= 1) v += __shfl_xor_sync(0xffffffffu, v, o);
    return v;
}

__global__ __launch_bounds__(256) void softmax2048_dual(
    float* __restrict__ S, float* __restrict__ Wt)
{
    __shared__ float red[8];
    const int b = blockIdx.x >> 11;
    const int q = blockIdx.x & 2047;
    float4* b4 = reinterpret_cast<float4*>(S + (long)blockIdx.x * 2048);

    float4 v0 = b4[threadIdx.x];
    float4 v1 = b4[threadIdx.x + 256];

    float m = fmaxf(fmaxf(fmaxf(v0.x, v0.y), fmaxf(v0.z, v0.w)),
                    fmaxf(fmaxf(v1.x, v1.y), fmaxf(v1.z, v1.w)));
    m = warpMax(m);
    const int wid = threadIdx.x >> 5, lid = threadIdx.x & 31;
    if (lid == 0) red[wid] = m;
    __syncthreads();
    float bm = red[0];
    #pragma unroll
    for (int i = 1; i < 8; i++) bm = fmaxf(bm, red[i]);
    __syncthreads();

    v0.x = __expf(v0.x - bm); v0.y = __expf(v0.y - bm);
    v0.z = __expf(v0.z - bm); v0.w = __expf(v0.w - bm);
    v1.x = __expf(v1.x - bm); v1.y = __expf(v1.y - bm);
    v1.z = __expf(v1.z - bm); v1.w = __expf(v1.w - bm);

    float s = (v0.x + v0.y) + (v0.z + v0.w) + (v1.x + v1.y) + (v1.z + v1.w);
    s = warpSum(s);
    if (lid == 0) red[wid] = s;
    __syncthreads();
    float bs = 0.f;
    #pragma unroll
    for (int i = 0; i < 8; i++) bs += red[i];
    const float inv = 1.0f / bs;

    v0.x *= inv; v0.y *= inv; v0.z *= inv; v0.w *= inv;
    v1.x *= inv; v1.y *= inv; v1.z *= inv; v1.w *= inv;
    b4[threadIdx.x]       = v0;
    b4[threadIdx.x + 256] = v1;

    // tiled copy: row q, cols 4*tid and 4*tid+1024
    float* wbase = Wt + (long)b * LQ_ * LK_
                 + ((long)(q >> 7) * (LK_ >> 5)) * TILE_FLOATS
                 + (q & 127) * 32;
    const int swz = (q & 7) << 2;
    {
        const int c = threadIdx.x * 4;
        float* p = wbase + (long)(c >> 5) * TILE_FLOATS + ((c & 31) ^ swz);
        *reinterpret_cast<float4*>(p) = v0;
    }
    {
        const int c = threadIdx.x * 4 + 1024;
        float* p = wbase + (long)(c >> 5) * TILE_FLOATS + ((c & 31) ^ swz);
        *reinterpret_cast<float4*>(p) = v1;
    }
}

// ---------------- launch ----------------
extern "C" void kernel_launch(void* const* d_in, const int* in_sizes, int n_in,
                              void* d_out, int out_size)
{
    const float* key   = (const float*)d_in[0];
    const float* query = (const float*)d_in[1];
    const float* value = (const float*)d_in[2];
    const float* W     = (const float*)d_in[3];
    // bias (d_in[4]): scalar added to every score -> softmax-invariant -> unused.

    float* weights = (float*)d_out;                   // [B, LQ, LK]
    float* ctx     = weights + (long)B_ * LQ_ * LK_;  // [B, LQ, DV]

    float *qT, *kT, *WtT, *vTT, *qWT, *wT;
    cudaGetSymbolAddress((void**)&qT,  g_qT);
    cudaGetSymbolAddress((void**)&kT,  g_kT);
    cudaGetSymbolAddress((void**)&WtT, g_WtT);
    cudaGetSymbolAddress((void**)&vTT, g_vTT);
    cudaGetSymbolAddress((void**)&qWT, g_qWT);
    cudaGetSymbolAddress((void**)&wT,  g_wT);

    cudaFuncSetAttribute(gemm3x_tf32<true>,  cudaFuncAttributeMaxDynamicSharedMemorySize, GEMM_SMEM);
    cudaFuncSetAttribute(gemm3x_tf32<false>, cudaFuncAttributeMaxDynamicSharedMemorySize, GEMM_SMEM);

    // pre-tiling
    retile<<<dim3(D_ / 32, (B_ * LQ_) / 128), 256>>>(query, qT, D_);
    retile<<<dim3(D_ / 32, (B_ * LK_) / 128), 256>>>(key,   kT, D_);
    transpose_tile<<<dim3(D_ / 32, D_ / 32, 1), 256>>>(W, WtT, D_, D_, 0, 0);
    transpose_tile<<<dim3(LK_ / 32, DV_ / 32, B_), 256>>>(
        value, vTT, LK_, DV_, (long)LK_ * DV_, (long)DV_ * LK_);

    // 1) qW = query @ W^T^T : [16384,1024] x [1024,1024], output tiled
    gemm3x_tf32<true><<<dim3(D_ / 128, (B_ * LQ_) / 128, 1), 256, GEMM_SMEM>>>(
        qT, WtT, qWT, B_ * LQ_, D_, D_, 0, 0, 0);

    // 2) scores = qW @ key^T (per batch) -> d_out weights region (row-major)
    gemm3x_tf32<false><<<dim3(LK_ / 128, LQ_ / 128, B_), 256, GEMM_SMEM>>>(
        qWT, kT, weights, LQ_, LK_, D_,
        (long)LQ_ * D_, (long)LK_ * D_, (long)LQ_ * LK_);

    // 3) softmax in place + tiled copy
    softmax2048_dual<<<B_ * LQ_, 256>>>(weights, wT);

    // 4) ctx = weights @ value (per batch)
    gemm3x_tf32<false><<<dim3(DV_ / 128, LQ_ / 128, B_), 256, GEMM_SMEM>>>(
        wT, vTT, ctx, LQ_, DV_, LK_,
        (long)LQ_ * LK_, (long)LK_ * DV_, (long)LQ_ * DV_);
}